// round 3
// baseline (speedup 1.0000x reference)
#include <cuda_runtime.h>
#include <cuda_bf16.h>
#include <math.h>

// Problem constants
#define BATCH   8192
#define DIM     1024      // DIM1 == DIM2
#define SKETCH  8192
#define OUT     512
#define LN_EPS  1e-5f

#define MCAP    1024      // |J| <= min(|image1|,|image2|) <= 1024
#define CCH     128       // column chunk for main kernel
#define NCHMAX  (MCAP/CCH)  // 8
#define TB      32        // batch rows per CTA in main kernel

// ---------------- device globals (scratch; no cudaMalloc allowed) ----------
__device__ unsigned int g_idx1[DIM];     // per input dim: (signbit<<31) | bucket
__device__ unsigned int g_idx2[DIM];
__device__ int          g_m;             // |J|
__device__ int          g_colJ[MCAP];    // compact c -> original column j
__device__ int          g_chunkptr1[NCHMAX + 1]; // entry ranges per chunk, side 1
__device__ int          g_chunkptr2[NCHMAX + 1];
__device__ unsigned int g_ent1[MCAP];    // packed entries: (c<<16)|(sign<<15)|i
__device__ unsigned int g_ent2[MCAP];
__device__ float        g_Wc[MCAP * OUT]; // compacted W rows (2 MB worst case)

// ---------------------------------------------------------------------------
// Kernel A: find the single nonzero per row of S1/S2.
// grid = 2*DIM blocks (one per row), 256 threads. Fully coalesced float4 scan.
// ---------------------------------------------------------------------------
__global__ void k_extract(const float* __restrict__ S1,
                          const float* __restrict__ S2)
{
    int row = blockIdx.x;
    const float* S;
    unsigned int* outp;
    if (row < DIM) { S = S1; outp = g_idx1; }
    else           { S = S2; outp = g_idx2; row -= DIM; }

    const float4* p = (const float4*)(S + (size_t)row * SKETCH);
    int t = threadIdx.x;
#pragma unroll
    for (int k = 0; k < SKETCH / 4 / 256; k++) {
        int v4 = t + k * 256;
        float4 v = p[v4];
        int base = v4 * 4;
        if (v.x != 0.0f) outp[row] = (unsigned)(base + 0) | (v.x < 0.0f ? 0x80000000u : 0u);
        if (v.y != 0.0f) outp[row] = (unsigned)(base + 1) | (v.y < 0.0f ? 0x80000000u : 0u);
        if (v.z != 0.0f) outp[row] = (unsigned)(base + 2) | (v.z < 0.0f ? 0x80000000u : 0u);
        if (v.w != 0.0f) outp[row] = (unsigned)(base + 3) | (v.w < 0.0f ? 0x80000000u : 0u);
    }
}

// ---------------------------------------------------------------------------
// Kernel B: build the compact structure. One CTA, 1024 threads.
//  - count bucket occupancy for both sides (packed into one int: lo16/hi16)
//  - J = buckets occupied on BOTH sides; compact index c assigned in j-order
//    via a block-wide prefix scan (deterministic up to fp-irrelevant details)
//  - per-side entry lists bucketed by chunk (c>>7), packed (c<<16)|(sign<<15)|i
// ---------------------------------------------------------------------------
__global__ void k_build()
{
    __shared__ int cnt[SKETCH];      // packed counts, then reused as colmap
    __shared__ int scanbuf[1024];
    __shared__ int sh_cp1[NCHMAX + 1], sh_cp2[NCHMAX + 1];
    __shared__ int offs1[NCHMAX], offs2[NCHMAX];
    __shared__ int ccnt1[NCHMAX], ccnt2[NCHMAX];

    int t = threadIdx.x;

    // zero counts
    for (int j = t; j < SKETCH; j += 1024) cnt[j] = 0;
    if (t < NCHMAX) { ccnt1[t] = 0; ccnt2[t] = 0; }
    __syncthreads();

    // occupancy counts
    {
        unsigned u1 = g_idx1[t] & (SKETCH - 1);
        unsigned u2 = g_idx2[t] & (SKETCH - 1);
        atomicAdd(&cnt[u1], 1);
        atomicAdd(&cnt[u2], 1 << 16);
    }
    __syncthreads();

    // qualification + prefix scan: thread t owns j in [t*8, t*8+8)
    int q = 0;
    int qual[8];
#pragma unroll
    for (int u = 0; u < 8; u++) {
        int j = t * 8 + u;
        int c = cnt[j];
        qual[u] = ((c & 0xFFFF) > 0 && (c >> 16) > 0) ? 1 : 0;
        q += qual[u];
    }
    scanbuf[t] = q;
    __syncthreads();
    for (int off = 1; off < 1024; off <<= 1) {
        int v = (t >= off) ? scanbuf[t - off] : 0;
        __syncthreads();
        scanbuf[t] += v;
        __syncthreads();
    }
    int excl = scanbuf[t] - q;
    int total = scanbuf[1023];

    // assign compact indices; overwrite cnt[j] with colmap (c or -1)
#pragma unroll
    for (int u = 0; u < 8; u++) {
        int j = t * 8 + u;
        if (qual[u]) {
            g_colJ[excl] = j;
            cnt[j] = excl;
            excl++;
        } else {
            cnt[j] = -1;
        }
    }
    if (t == 0) g_m = total;
    __syncthreads();

    // per-chunk entry counts
    {
        unsigned u1 = g_idx1[t];
        int c1 = cnt[u1 & (SKETCH - 1)];
        if (c1 >= 0) atomicAdd(&ccnt1[c1 >> 7], 1);
        unsigned u2 = g_idx2[t];
        int c2 = cnt[u2 & (SKETCH - 1)];
        if (c2 >= 0) atomicAdd(&ccnt2[c2 >> 7], 1);
    }
    __syncthreads();

    if (t == 0) {
        int s1 = 0, s2 = 0;
        for (int k = 0; k < NCHMAX; k++) {
            sh_cp1[k] = s1; offs1[k] = s1; s1 += ccnt1[k];
            sh_cp2[k] = s2; offs2[k] = s2; s2 += ccnt2[k];
        }
        sh_cp1[NCHMAX] = s1;
        sh_cp2[NCHMAX] = s2;
        for (int k = 0; k <= NCHMAX; k++) {
            g_chunkptr1[k] = sh_cp1[k];
            g_chunkptr2[k] = sh_cp2[k];
        }
    }
    __syncthreads();

    // fill packed entry lists
    {
        unsigned u1 = g_idx1[t];
        int c1 = cnt[u1 & (SKETCH - 1)];
        if (c1 >= 0) {
            int slot = atomicAdd(&offs1[c1 >> 7], 1);
            unsigned sign = (u1 >> 31) & 1u;
            g_ent1[slot] = ((unsigned)c1 << 16) | (sign << 15) | (unsigned)t;
        }
        unsigned u2 = g_idx2[t];
        int c2 = cnt[u2 & (SKETCH - 1)];
        if (c2 >= 0) {
            int slot = atomicAdd(&offs2[c2 >> 7], 1);
            unsigned sign = (u2 >> 31) & 1u;
            g_ent2[slot] = ((unsigned)c2 << 16) | (sign << 15) | (unsigned)t;
        }
    }
}

// ---------------------------------------------------------------------------
// Kernel B2: gather compacted W rows. grid = MCAP blocks x OUT threads.
// ---------------------------------------------------------------------------
__global__ void k_wgather(const float* __restrict__ W)
{
    int c = blockIdx.x;
    if (c < g_m) {
        g_Wc[(size_t)c * OUT + threadIdx.x] =
            W[(size_t)g_colJ[c] * OUT + threadIdx.x];
    }
}

// ---------------------------------------------------------------------------
// Main fused kernel: per CTA, TB=32 batch rows, 256 threads.
//  Phase 1 per chunk: scatter-accumulate s1/s2 into shared (float atomics,
//                     independent loads -> high MLP), elementwise product.
//  Phase 2 per chunk: register-tiled FFMA GEMM [32 x Cn] @ [Cn x 512],
//                     8x8 micro-tile per thread (thread grid 4 x 64).
//  Epilogue: bias already folded into acc init; LayerNorm + ReLU; store.
// ---------------------------------------------------------------------------
__global__ __launch_bounds__(256)
void k_main(const float* __restrict__ x1, const float* __restrict__ x2,
            const float* __restrict__ bias, const float* __restrict__ gamma,
            const float* __restrict__ beta, float* __restrict__ out)
{
    __shared__ float s1c[CCH * TB];
    __shared__ float s2c[CCH * TB];     // reused as LN reduction buffer
    __shared__ unsigned int sh_e1[MCAP];
    __shared__ unsigned int sh_e2[MCAP];
    __shared__ int sh_cp1[NCHMAX + 1], sh_cp2[NCHMAX + 1];
    __shared__ int sh_m;
    __shared__ float sh_mu[TB], sh_rs[TB];

    int tid = threadIdx.x;
    int b0  = blockIdx.x * TB;
    int tc  = tid & 63;          // output-column group
    int o0  = tc * 8;
    int r0g = (tid >> 6) * 8;    // row group (0,8,16,24)

    if (tid <= NCHMAX) { sh_cp1[tid] = g_chunkptr1[tid]; sh_cp2[tid] = g_chunkptr2[tid]; }
    if (tid == 0) sh_m = g_m;
    for (int q2 = tid; q2 < MCAP; q2 += 256) {
        sh_e1[q2] = g_ent1[q2];
        sh_e2[q2] = g_ent2[q2];
    }
    __syncthreads();

    int m = sh_m;
    int nch = (m + CCH - 1) / CCH;

    // accumulators, initialized with bias (so LN stats include it)
    float acc[8][8];
    {
        float4 ba = *(const float4*)(bias + o0);
        float4 bb = *(const float4*)(bias + o0 + 4);
        float bi[8] = {ba.x, ba.y, ba.z, ba.w, bb.x, bb.y, bb.z, bb.w};
#pragma unroll
        for (int j = 0; j < 8; j++)
#pragma unroll
            for (int k = 0; k < 8; k++) acc[j][k] = bi[k];
    }

    for (int ch = 0; ch < nch; ch++) {
        int ck0 = ch * CCH;
        int Cn  = min(CCH, m - ck0);

        // zero the chunk accumulators
        for (int q2 = tid; q2 < Cn * TB; q2 += 256) { s1c[q2] = 0.0f; s2c[q2] = 0.0f; }
        __syncthreads();

        // scatter side 1
        {
            int e0 = sh_cp1[ch], e1 = sh_cp1[ch + 1];
            int nw = (e1 - e0) * TB;
            for (int p = tid; p < nw; p += 256) {
                unsigned u = sh_e1[e0 + (p >> 5)];
                int r  = p & 31;
                int cl = (int)(u >> 16) - ck0;
                int i  = (int)(u & 1023u);
                float x = x1[(size_t)(b0 + r) * DIM + i];
                float v = (u & 0x8000u) ? -x : x;
                atomicAdd(&s1c[cl * TB + r], v);
            }
        }
        // scatter side 2
        {
            int e0 = sh_cp2[ch], e1 = sh_cp2[ch + 1];
            int nw = (e1 - e0) * TB;
            for (int p = tid; p < nw; p += 256) {
                unsigned u = sh_e2[e0 + (p >> 5)];
                int r  = p & 31;
                int cl = (int)(u >> 16) - ck0;
                int i  = (int)(u & 1023u);
                float x = x2[(size_t)(b0 + r) * DIM + i];
                float v = (u & 0x8000u) ? -x : x;
                atomicAdd(&s2c[cl * TB + r], v);
            }
        }
        __syncthreads();

        // v = s1 * s2 (in place into s1c)
        for (int q2 = tid; q2 < Cn * TB; q2 += 256) s1c[q2] *= s2c[q2];
        __syncthreads();

        // GEMM: acc += v[32 x Cn] @ Wc[Cn x 512] (micro 8x8 per thread)
        const float* Wp = g_Wc + (size_t)ck0 * OUT + o0;
        for (int cl = 0; cl < Cn; cl++) {
            float4 va = *(const float4*)&s1c[cl * TB + r0g];
            float4 vb = *(const float4*)&s1c[cl * TB + r0g + 4];
            float4 wa = *(const float4*)(Wp + (size_t)cl * OUT);
            float4 wb = *(const float4*)(Wp + (size_t)cl * OUT + 4);
            float vv[8] = {va.x, va.y, va.z, va.w, vb.x, vb.y, vb.z, vb.w};
            float ww[8] = {wa.x, wa.y, wa.z, wa.w, wb.x, wb.y, wb.z, wb.w};
#pragma unroll
            for (int j = 0; j < 8; j++)
#pragma unroll
                for (int k = 0; k < 8; k++) acc[j][k] += vv[j] * ww[k];
        }
        __syncthreads();   // s1c/s2c rewritten next chunk (or reused by LN)
    }

    // -------- LayerNorm reduction across the 64 column-group threads -------
    float* red_s = s2c;          // [TB][64]
    float* red_q = s2c + TB * 64;
#pragma unroll
    for (int j = 0; j < 8; j++) {
        float s = 0.0f, q = 0.0f;
#pragma unroll
        for (int k = 0; k < 8; k++) { float h = acc[j][k]; s += h; q += h * h; }
        red_s[(r0g + j) * 64 + tc] = s;
        red_q[(r0g + j) * 64 + tc] = q;
    }
    __syncthreads();
    if (tid < TB) {
        float s = 0.0f, q = 0.0f;
        for (int u = 0; u < 64; u++) {
            int u2 = (u + tid) & 63;            // skew to avoid bank conflicts
            s += red_s[tid * 64 + u2];
            q += red_q[tid * 64 + u2];
        }
        float mu  = s * (1.0f / OUT);
        float var = q * (1.0f / OUT) - mu * mu;
        sh_mu[tid] = mu;
        sh_rs[tid] = rsqrtf(var + LN_EPS);
    }
    __syncthreads();

    // -------- normalize, affine, ReLU, store -------------------------------
    float4 ga4 = *(const float4*)(gamma + o0);
    float4 gb4 = *(const float4*)(gamma + o0 + 4);
    float4 ba4 = *(const float4*)(beta + o0);
    float4 bb4 = *(const float4*)(beta + o0 + 4);
    float ga[8] = {ga4.x, ga4.y, ga4.z, ga4.w, gb4.x, gb4.y, gb4.z, gb4.w};
    float be[8] = {ba4.x, ba4.y, ba4.z, ba4.w, bb4.x, bb4.y, bb4.z, bb4.w};

#pragma unroll
    for (int j = 0; j < 8; j++) {
        float mu = sh_mu[r0g + j];
        float rs = sh_rs[r0g + j];
        float o[8];
#pragma unroll
        for (int k = 0; k < 8; k++) {
            float v = (acc[j][k] - mu) * rs * ga[k] + be[k];
            o[k] = fmaxf(v, 0.0f);
        }
        float* dst = out + (size_t)(b0 + r0g + j) * OUT + o0;
        *(float4*)(dst)     = make_float4(o[0], o[1], o[2], o[3]);
        *(float4*)(dst + 4) = make_float4(o[4], o[5], o[6], o[7]);
    }
}

// ---------------------------------------------------------------------------
extern "C" void kernel_launch(void* const* d_in, const int* in_sizes, int n_in,
                              void* d_out, int out_size)
{
    const float* x1    = (const float*)d_in[0];
    const float* x2    = (const float*)d_in[1];
    const float* S1    = (const float*)d_in[2];
    const float* S2    = (const float*)d_in[3];
    const float* W     = (const float*)d_in[4];
    const float* b     = (const float*)d_in[5];
    const float* gamma = (const float*)d_in[6];
    const float* beta  = (const float*)d_in[7];
    float* out = (float*)d_out;

    k_extract<<<2 * DIM, 256>>>(S1, S2);
    k_build<<<1, 1024>>>();
    k_wgather<<<MCAP, OUT>>>(W);
    k_main<<<BATCH / TB, 256>>>(x1, x2, b, gamma, beta, out);
}

// round 4
// speedup vs baseline: 1.1242x; 1.1242x over previous
#include <cuda_runtime.h>
#include <cuda_bf16.h>
#include <math.h>

// Problem constants
#define BATCH   8192
#define DIM     1024      // DIM1 == DIM2
#define SKETCH  8192
#define OUT     512
#define LN_EPS  1e-5f

#define MCAP    1024      // |J| <= 1024
#define CCH     128       // column chunk for main kernel
#define NCHMAX  (MCAP/CCH)
#define TB      32        // batch rows per CTA in main kernel

// ---------------- device globals (scratch; no cudaMalloc allowed) ----------
__device__ unsigned int g_idx1[DIM];     // per input dim: (signbit<<31) | bucket
__device__ unsigned int g_idx2[DIM];
__device__ int          g_m;             // |J|
__device__ int          g_colJ[MCAP];    // compact c -> original column j
__device__ int          g_cp1[MCAP + 1]; // CSR col ptrs, side 1
__device__ int          g_cp2[MCAP + 1];
__device__ unsigned int g_ent1[MCAP];    // CSR entries: (sign<<15) | i
__device__ unsigned int g_ent2[MCAP];
__device__ float        g_Wc[MCAP * OUT]; // compacted W rows

// -------- f32x2 packed-FMA helpers (PTX-only; ptxas never emits these) -----
__device__ __forceinline__ unsigned long long pack2(float lo, float hi) {
    unsigned long long r;
    asm("mov.b64 %0, {%1, %2};" : "=l"(r) : "f"(lo), "f"(hi));
    return r;
}
__device__ __forceinline__ void unpack2(unsigned long long v, float& lo, float& hi) {
    asm("mov.b64 {%0, %1}, %2;" : "=f"(lo), "=f"(hi) : "l"(v));
}
__device__ __forceinline__ unsigned long long ffma2(unsigned long long a,
                                                    unsigned long long b,
                                                    unsigned long long c) {
    unsigned long long d;
    asm("fma.rn.f32x2 %0, %1, %2, %3;" : "=l"(d) : "l"(a), "l"(b), "l"(c));
    return d;
}

// ---------------------------------------------------------------------------
// Kernel A: find the single nonzero per row of S1/S2. Coalesced float4 scan.
// ---------------------------------------------------------------------------
__global__ void k_extract(const float* __restrict__ S1,
                          const float* __restrict__ S2)
{
    int row = blockIdx.x;
    const float* S;
    unsigned int* outp;
    if (row < DIM) { S = S1; outp = g_idx1; }
    else           { S = S2; outp = g_idx2; row -= DIM; }

    const float4* p = (const float4*)(S + (size_t)row * SKETCH);
    int t = threadIdx.x;
#pragma unroll
    for (int k = 0; k < SKETCH / 4 / 256; k++) {
        int v4 = t + k * 256;
        float4 v = p[v4];
        int base = v4 * 4;
        if (v.x != 0.0f) outp[row] = (unsigned)(base + 0) | (v.x < 0.0f ? 0x80000000u : 0u);
        if (v.y != 0.0f) outp[row] = (unsigned)(base + 1) | (v.y < 0.0f ? 0x80000000u : 0u);
        if (v.z != 0.0f) outp[row] = (unsigned)(base + 2) | (v.z < 0.0f ? 0x80000000u : 0u);
        if (v.w != 0.0f) outp[row] = (unsigned)(base + 3) | (v.w < 0.0f ? 0x80000000u : 0u);
    }
}

// ---------------------------------------------------------------------------
// Kernel B: build compact structure + per-column CSR. One CTA, 1024 threads.
// ---------------------------------------------------------------------------
__global__ void k_build()
{
    __shared__ int cnt[SKETCH];      // packed occupancy counts, then colmap
    __shared__ int scanbuf[1024];
    __shared__ int colcnt[MCAP];     // per-column entry counts / running offsets

    int t = threadIdx.x;

    for (int j = t; j < SKETCH; j += 1024) cnt[j] = 0;
    __syncthreads();

    unsigned u1 = g_idx1[t];
    unsigned u2 = g_idx2[t];
    atomicAdd(&cnt[u1 & (SKETCH - 1)], 1);
    atomicAdd(&cnt[u2 & (SKETCH - 1)], 1 << 16);
    __syncthreads();

    // qualification + prefix scan: thread t owns j in [t*8, t*8+8)
    int q = 0;
    int qual[8];
#pragma unroll
    for (int u = 0; u < 8; u++) {
        int j = t * 8 + u;
        int c = cnt[j];
        qual[u] = ((c & 0xFFFF) > 0 && (c >> 16) > 0) ? 1 : 0;
        q += qual[u];
    }
    scanbuf[t] = q;
    __syncthreads();
    for (int off = 1; off < 1024; off <<= 1) {
        int v = (t >= off) ? scanbuf[t - off] : 0;
        __syncthreads();
        scanbuf[t] += v;
        __syncthreads();
    }
    int excl = scanbuf[t] - q;
    int total = scanbuf[1023];

#pragma unroll
    for (int u = 0; u < 8; u++) {
        int j = t * 8 + u;
        if (qual[u]) { g_colJ[excl] = j; cnt[j] = excl; excl++; }
        else         { cnt[j] = -1; }
    }
    if (t == 0) g_m = total;
    __syncthreads();

    // CSR build for both sides
    int c1 = cnt[u1 & (SKETCH - 1)];
    int c2 = cnt[u2 & (SKETCH - 1)];
#pragma unroll
    for (int s = 0; s < 2; s++) {
        int cc = s ? c2 : c1;
        unsigned uu = s ? u2 : u1;
        int* cp = s ? g_cp2 : g_cp1;
        unsigned int* ent = s ? g_ent2 : g_ent1;

        colcnt[t] = 0;
        __syncthreads();
        if (cc >= 0) atomicAdd(&colcnt[cc], 1);
        __syncthreads();

        int myc = colcnt[t];
        scanbuf[t] = myc;
        __syncthreads();
        for (int off = 1; off < 1024; off <<= 1) {
            int v = (t >= off) ? scanbuf[t - off] : 0;
            __syncthreads();
            scanbuf[t] += v;
            __syncthreads();
        }
        int ex = scanbuf[t] - myc;
        cp[t] = ex;
        if (t == 1023) cp[1024] = scanbuf[1023];
        colcnt[t] = ex;      // running offsets
        __syncthreads();
        if (cc >= 0) {
            int slot = atomicAdd(&colcnt[cc], 1);
            ent[slot] = (((uu >> 31) & 1u) << 15) | (unsigned)t;
        }
        __syncthreads();
    }
}

// ---------------------------------------------------------------------------
// Kernel B2: gather compacted W rows.
// ---------------------------------------------------------------------------
__global__ void k_wgather(const float* __restrict__ W)
{
    int c = blockIdx.x;
    if (c < g_m) {
        g_Wc[(size_t)c * OUT + threadIdx.x] =
            W[(size_t)g_colJ[c] * OUT + threadIdx.x];
    }
}

// ---------------------------------------------------------------------------
// Main fused kernel. TB=32 rows/CTA, 256 threads, 256 CTAs (all resident).
//  Phase 1 (per chunk): CSR gather — each thread computes s1,s2 for (c,r) and
//                       writes product directly. No atomics, no zero pass.
//  Phase 2: register GEMM with packed fma.rn.f32x2 (rows paired in the b64).
//  Epilogue: LayerNorm (+bias folded into acc init) + ReLU.
// ---------------------------------------------------------------------------
__global__ __launch_bounds__(256)
void k_main(const float* __restrict__ x1, const float* __restrict__ x2,
            const float* __restrict__ bias, const float* __restrict__ gamma,
            const float* __restrict__ beta, float* __restrict__ out)
{
    __shared__ float s1c[CCH * TB];          // product tile [Cn][TB]; LN buffer
    __shared__ int sh_cp1[MCAP + 1], sh_cp2[MCAP + 1];
    __shared__ unsigned int sh_e1[MCAP], sh_e2[MCAP];
    __shared__ float sh_mu[TB], sh_rs[TB];
    __shared__ int sh_m;

    int tid = threadIdx.x;
    int b0  = blockIdx.x * TB;
    int tc  = tid & 63;          // output-column group (64 groups x 8 cols)
    int o0  = tc * 8;
    int r0g = (tid >> 6) * 8;    // row group (0,8,16,24)

    for (int i = tid; i < MCAP + 1; i += 256) {
        sh_cp1[i] = g_cp1[i];
        sh_cp2[i] = g_cp2[i];
    }
    for (int i = tid; i < MCAP; i += 256) {
        sh_e1[i] = g_ent1[i];
        sh_e2[i] = g_ent2[i];
    }
    if (tid == 0) sh_m = g_m;
    __syncthreads();

    int m = sh_m;
    int nch = (m + CCH - 1) / CCH;

    // accumulators: acc2[jp][k] holds rows (r0g+2jp, r0g+2jp+1) packed, col o0+k
    unsigned long long acc2[4][8];
    {
        float4 ba = *(const float4*)(bias + o0);
        float4 bb = *(const float4*)(bias + o0 + 4);
        float bi[8] = {ba.x, ba.y, ba.z, ba.w, bb.x, bb.y, bb.z, bb.w};
#pragma unroll
        for (int k = 0; k < 8; k++) {
            unsigned long long b2 = pack2(bi[k], bi[k]);
#pragma unroll
            for (int jp = 0; jp < 4; jp++) acc2[jp][k] = b2;
        }
    }

    for (int ch = 0; ch < nch; ch++) {
        int ck0 = ch * CCH;
        int Cn  = min(CCH, m - ck0);

        // ---- gather: v[c][r] = s1(c,r) * s2(c,r), no atomics ----
        {
            int nw = Cn * TB;
#pragma unroll 2
            for (int p = tid; p < nw; p += 256) {
                int cl = p >> 5;
                int r  = p & 31;
                int c  = ck0 + cl;
                size_t rowoff = (size_t)(b0 + r) * DIM;

                float s1 = 0.0f;
                int e0 = sh_cp1[c], e1 = sh_cp1[c + 1];
                for (int e = e0; e < e1; e++) {
                    unsigned u = sh_e1[e];
                    float x = __ldg(&x1[rowoff + (u & 1023u)]);
                    s1 += (u & 0x8000u) ? -x : x;
                }
                float s2 = 0.0f;
                int f0 = sh_cp2[c], f1 = sh_cp2[c + 1];
                for (int e = f0; e < f1; e++) {
                    unsigned u = sh_e2[e];
                    float x = __ldg(&x2[rowoff + (u & 1023u)]);
                    s2 += (u & 0x8000u) ? -x : x;
                }
                s1c[cl * TB + r] = s1 * s2;
            }
        }
        __syncthreads();

        // ---- GEMM: acc += v[32 x Cn] @ Wc[Cn x 512], packed f32x2 ----
        const float* Wp = g_Wc + (size_t)ck0 * OUT + o0;
#pragma unroll 2
        for (int cl = 0; cl < Cn; cl++) {
            // row pairs: adjacent floats in smem -> direct b64 loads, no packs
            const ulonglong2* vp =
                (const ulonglong2*)&s1c[cl * TB + r0g];
            ulonglong2 va = vp[0];
            ulonglong2 vb = vp[1];
            unsigned long long vv2[4] = {va.x, va.y, vb.x, vb.y};

            float4 wa = __ldg((const float4*)(Wp + (size_t)cl * OUT));
            float4 wb = __ldg((const float4*)(Wp + (size_t)cl * OUT + 4));
            float ww[8] = {wa.x, wa.y, wa.z, wa.w, wb.x, wb.y, wb.z, wb.w};
#pragma unroll
            for (int k = 0; k < 8; k++) {
                unsigned long long w2 = pack2(ww[k], ww[k]);
#pragma unroll
                for (int jp = 0; jp < 4; jp++)
                    acc2[jp][k] = ffma2(vv2[jp], w2, acc2[jp][k]);
            }
        }
        __syncthreads();   // s1c rewritten next chunk (or reused by LN)
    }

    // -------- LayerNorm reduction across the 64 column-group threads -------
    float* red_s = s1c;              // [TB][64]
    float* red_q = s1c + TB * 64;
#pragma unroll
    for (int jp = 0; jp < 4; jp++) {
        float slo = 0.0f, qlo = 0.0f, shi = 0.0f, qhi = 0.0f;
#pragma unroll
        for (int k = 0; k < 8; k++) {
            float lo, hi;
            unpack2(acc2[jp][k], lo, hi);
            slo += lo; qlo += lo * lo;
            shi += hi; qhi += hi * hi;
        }
        int rlo = r0g + 2 * jp, rhi = rlo + 1;
        red_s[rlo * 64 + tc] = slo;
        red_q[rlo * 64 + tc] = qlo;
        red_s[rhi * 64 + tc] = shi;
        red_q[rhi * 64 + tc] = qhi;
    }
    __syncthreads();
    if (tid < TB) {
        float s = 0.0f, q = 0.0f;
        for (int u = 0; u < 64; u++) {
            int u2 = (u + tid) & 63;            // skew to avoid bank conflicts
            s += red_s[tid * 64 + u2];
            q += red_q[tid * 64 + u2];
        }
        float mu  = s * (1.0f / OUT);
        float var = q * (1.0f / OUT) - mu * mu;
        sh_mu[tid] = mu;
        sh_rs[tid] = rsqrtf(var + LN_EPS);
    }
    __syncthreads();

    // -------- normalize, affine, ReLU, store -------------------------------
    float4 ga4 = *(const float4*)(gamma + o0);
    float4 gb4 = *(const float4*)(gamma + o0 + 4);
    float4 ba4 = *(const float4*)(beta + o0);
    float4 bb4 = *(const float4*)(beta + o0 + 4);
    float ga[8] = {ga4.x, ga4.y, ga4.z, ga4.w, gb4.x, gb4.y, gb4.z, gb4.w};
    float be[8] = {ba4.x, ba4.y, ba4.z, ba4.w, bb4.x, bb4.y, bb4.z, bb4.w};

#pragma unroll
    for (int jp = 0; jp < 4; jp++) {
        int rlo = r0g + 2 * jp;
        float mulo = sh_mu[rlo],     rslo = sh_rs[rlo];
        float muhi = sh_mu[rlo + 1], rshi = sh_rs[rlo + 1];
        float olo[8], ohi[8];
#pragma unroll
        for (int k = 0; k < 8; k++) {
            float lo, hi;
            unpack2(acc2[jp][k], lo, hi);
            olo[k] = fmaxf((lo - mulo) * rslo * ga[k] + be[k], 0.0f);
            ohi[k] = fmaxf((hi - muhi) * rshi * ga[k] + be[k], 0.0f);
        }
        float* dlo = out + (size_t)(b0 + rlo) * OUT + o0;
        float* dhi = out + (size_t)(b0 + rlo + 1) * OUT + o0;
        *(float4*)(dlo)     = make_float4(olo[0], olo[1], olo[2], olo[3]);
        *(float4*)(dlo + 4) = make_float4(olo[4], olo[5], olo[6], olo[7]);
        *(float4*)(dhi)     = make_float4(ohi[0], ohi[1], ohi[2], ohi[3]);
        *(float4*)(dhi + 4) = make_float4(ohi[4], ohi[5], ohi[6], ohi[7]);
    }
}

// ---------------------------------------------------------------------------
extern "C" void kernel_launch(void* const* d_in, const int* in_sizes, int n_in,
                              void* d_out, int out_size)
{
    const float* x1    = (const float*)d_in[0];
    const float* x2    = (const float*)d_in[1];
    const float* S1    = (const float*)d_in[2];
    const float* S2    = (const float*)d_in[3];
    const float* W     = (const float*)d_in[4];
    const float* b     = (const float*)d_in[5];
    const float* gamma = (const float*)d_in[6];
    const float* beta  = (const float*)d_in[7];
    float* out = (float*)d_out;

    k_extract<<<2 * DIM, 256>>>(S1, S2);
    k_build<<<1, 1024>>>();
    k_wgather<<<MCAP, OUT>>>(W);
    k_main<<<BATCH / TB, 256>>>(x1, x2, b, gamma, beta, out);
}